// round 2
// baseline (speedup 1.0000x reference)
#include <cuda_runtime.h>
#include <math.h>

// ---------------- problem constants ----------------
#define BATCH  2
#define LSEQ   8192
#define DMODEL 1024
#define NPROJ  6176    // 2*D_INNER + 2*NQK*DSTATE + NV
#define CONVD  5120    // D_INNER + 2*NQK*DSTATE
#define DINNER 1024
#define NH     32      // NQK == NV
#define DST    64
#define HDIM   32
#define CHK    128
#define NCH    64      // chunks per sequence
#define MROWS  (BATCH*LSEQ)   // 16384

// ---------------- scratch (device globals; no allocations allowed) --------
__device__ float g_xbcza[(size_t)MROWS * NPROJ];   // in-proj output  (~404 MB)
__device__ float g_conv [(size_t)MROWS * CONVD];   // conv output     (~335 MB)
__device__ float g_acum [(size_t)MROWS * NH];      // within-chunk cumsum of -dt
__device__ float g_y    [(size_t)MROWS * DINNER];  // y (diag, then gated)
__device__ float g_states[(size_t)BATCH*NCH*NH*HDIM*DST]; // per-chunk states
__device__ float g_prevs [(size_t)BATCH*NCH*NH*HDIM*DST]; // scan outputs
__device__ float g_dc   [BATCH*NCH*NH];            // per-chunk decay

// ============================================================
// Kernel 1/6: C[M,N] = A[M,K] @ B[N,K]^T   (both row-major, K contiguous)
// 128x128 tile, BK=16, 256 threads, 8x8 micro-tile.
// ============================================================
__global__ __launch_bounds__(256)
void sgemm_nt(const float* __restrict__ A, const float* __restrict__ B,
              float* __restrict__ C, int M, int N, int K)
{
    __shared__ float As[16][132];
    __shared__ float Bs[16][132];

    const int tid = threadIdx.x;
    const int tx  = tid & 15;
    const int ty  = tid >> 4;
    const int m0  = blockIdx.y * 128;
    const int n0  = blockIdx.x * 128;

    const int lrow = tid >> 2;          // 0..63
    const int lcol = (tid & 3) * 4;     // 0,4,8,12

    float acc[8][8];
#pragma unroll
    for (int i = 0; i < 8; i++)
#pragma unroll
        for (int j = 0; j < 8; j++) acc[i][j] = 0.f;

    for (int k0 = 0; k0 < K; k0 += 16) {
#pragma unroll
        for (int r = 0; r < 2; r++) {
            int row = lrow + r * 64;
            // A tile (rows always in-bounds for our sizes)
            float4 va = *(const float4*)&A[(size_t)(m0 + row) * K + k0 + lcol];
            As[lcol + 0][row] = va.x;
            As[lcol + 1][row] = va.y;
            As[lcol + 2][row] = va.z;
            As[lcol + 3][row] = va.w;
            // B tile (guard N edge)
            int nrow = n0 + row;
            float4 vb = make_float4(0.f, 0.f, 0.f, 0.f);
            if (nrow < N)
                vb = *(const float4*)&B[(size_t)nrow * K + k0 + lcol];
            Bs[lcol + 0][row] = vb.x;
            Bs[lcol + 1][row] = vb.y;
            Bs[lcol + 2][row] = vb.z;
            Bs[lcol + 3][row] = vb.w;
        }
        __syncthreads();

#pragma unroll
        for (int kk = 0; kk < 16; kk++) {
            float a[8], bb[8];
            float4 a0 = *(const float4*)&As[kk][ty * 8];
            float4 a1 = *(const float4*)&As[kk][ty * 8 + 4];
            float4 b0 = *(const float4*)&Bs[kk][tx * 8];
            float4 b1 = *(const float4*)&Bs[kk][tx * 8 + 4];
            a[0]=a0.x; a[1]=a0.y; a[2]=a0.z; a[3]=a0.w;
            a[4]=a1.x; a[5]=a1.y; a[6]=a1.z; a[7]=a1.w;
            bb[0]=b0.x; bb[1]=b0.y; bb[2]=b0.z; bb[3]=b0.w;
            bb[4]=b1.x; bb[5]=b1.y; bb[6]=b1.z; bb[7]=b1.w;
#pragma unroll
            for (int i = 0; i < 8; i++)
#pragma unroll
                for (int j = 0; j < 8; j++)
                    acc[i][j] += a[i] * bb[j];
        }
        __syncthreads();
    }

#pragma unroll
    for (int i = 0; i < 8; i++) {
        int m = m0 + ty * 8 + i;
#pragma unroll
        for (int jj = 0; jj < 8; jj += 4) {
            int n = n0 + tx * 8 + jj;
            if (n < N) {  // N is a multiple of 32 -> whole float4 valid
                float4 v = make_float4(acc[i][jj], acc[i][jj+1], acc[i][jj+2], acc[i][jj+3]);
                *(float4*)&C[(size_t)m * N + n] = v;
            }
        }
    }
}

// ============================================================
// Kernel 2: depthwise causal conv (DCONV=4) + bias over CONVD channels
// ============================================================
__global__ __launch_bounds__(256)
void conv_kernel(const float* __restrict__ cw, const float* __restrict__ cb)
{
    int ch = blockIdx.x * 256 + threadIdx.x;   // < 5120 exactly
    int m  = blockIdx.y;
    int t  = m & (LSEQ - 1);

    const float* base = g_xbcza + (size_t)m * NPROJ + ch;
    float acc = cb[ch];
#pragma unroll
    for (int k = 0; k < 4; k++) {
        int tt = t - 3 + k;
        if (tt >= 0)
            acc += cw[ch * 4 + k] * base[(long)(k - 3) * NPROJ];
    }
    g_conv[(size_t)m * CONVD + ch] = acc;
}

// ============================================================
// Kernel 3: per-(b,chunk,head): dt+cumsum, G=C.B^T, mask*decay, Y_diag=M@X,
//           chunk states. Dynamic smem ~151 KB.
// ============================================================
__global__ __launch_bounds__(256)
void chunk_kernel()
{
    extern __shared__ float sm[];
    float* CsT = sm;               // [64][132]
    float* BsT = sm + 8448;        // [64][132]
    float* Xs  = sm + 16896;       // [128][36]
    float* MsT = sm + 21504;       // [128][132]  (M transposed: [s][l])
    float* sA  = sm + 38400;       // [128] cumsum (negated)
    float* sDs = sm + 38528;       // [128] decay_states

    const int tid = threadIdx.x;
    const int bid = blockIdx.x;
    const int h = bid & 31;
    const int c = (bid >> 5) & 63;
    const int b = bid >> 11;
    const size_t m0 = (size_t)b * LSEQ + (size_t)c * CHK;

    // ---- load B,C (transposed) and X tiles ----
    {
        int n = tid & 63, lb = tid >> 6;
        for (int l = lb; l < CHK; l += 4) {
            const float* row = &g_conv[(m0 + l) * CONVD];
            BsT[n * 132 + l] = row[DINNER + h * DST + n];
            CsT[n * 132 + l] = row[DINNER + NH * DST + h * DST + n];
        }
        int p = tid & 31, lb2 = tid >> 5;
        for (int l = lb2; l < CHK; l += 8)
            Xs[l * 36 + p] = g_conv[(m0 + l) * CONVD + h * HDIM + p];
    }

    // ---- dt = softplus(A_log); inclusive scan of -dt ----
    if (tid < CHK) {
        float alog = g_xbcza[(m0 + tid) * NPROJ + (CONVD + DINNER) + h];
        float dt = alog > 20.f ? alog : log1pf(expf(alog));
        sA[tid] = dt;
    }
    __syncthreads();
    for (int off = 1; off < CHK; off <<= 1) {
        float v = 0.f;
        if (tid < CHK && tid >= off) v = sA[tid - off];
        __syncthreads();
        if (tid < CHK) sA[tid] += v;
        __syncthreads();
    }
    if (tid < CHK) sA[tid] = -sA[tid];
    __syncthreads();
    float aLast = sA[CHK - 1];
    if (tid < CHK) {
        sDs[tid] = __expf(aLast - sA[tid]);
        g_acum[(m0 + tid) * NH + h] = sA[tid];
    }
    if (tid == 0) g_dc[(b * NCH + c) * NH + h] = __expf(aLast);
    __syncthreads();

    // ---- phase 1: G = C.B^T over DST, apply decay+mask, write MsT[s][l] ----
    const int txp = tid & 15, typ = tid >> 4;
    const int l0 = typ * 8, s0 = txp * 8;
    if (typ < txp) {
#pragma unroll
        for (int j = 0; j < 8; j++)
#pragma unroll
            for (int i = 0; i < 8; i++)
                MsT[(s0 + j) * 132 + l0 + i] = 0.f;
    } else {
        float acc[8][8];
#pragma unroll
        for (int i = 0; i < 8; i++)
#pragma unroll
            for (int j = 0; j < 8; j++) acc[i][j] = 0.f;

        for (int n = 0; n < DST; n++) {
            float a[8], bb[8];
            float4 t0 = *(float4*)&CsT[n * 132 + l0];
            float4 t1 = *(float4*)&CsT[n * 132 + l0 + 4];
            float4 u0 = *(float4*)&BsT[n * 132 + s0];
            float4 u1 = *(float4*)&BsT[n * 132 + s0 + 4];
            a[0]=t0.x; a[1]=t0.y; a[2]=t0.z; a[3]=t0.w;
            a[4]=t1.x; a[5]=t1.y; a[6]=t1.z; a[7]=t1.w;
            bb[0]=u0.x; bb[1]=u0.y; bb[2]=u0.z; bb[3]=u0.w;
            bb[4]=u1.x; bb[5]=u1.y; bb[6]=u1.z; bb[7]=u1.w;
#pragma unroll
            for (int i = 0; i < 8; i++)
#pragma unroll
                for (int j = 0; j < 8; j++)
                    acc[i][j] += a[i] * bb[j];
        }
        // tile-rebased decay: exp(a_l - a_s) = exp(a_l - a_{s0}) * exp(a_{s0} - a_s)
        float as0 = sA[s0];
        float el[8], es[8];
#pragma unroll
        for (int i = 0; i < 8; i++) el[i] = __expf(sA[l0 + i] - as0);
#pragma unroll
        for (int j = 0; j < 8; j++) es[j] = __expf(as0 - sA[s0 + j]);
#pragma unroll
        for (int j = 0; j < 8; j++)
#pragma unroll
            for (int i = 0; i < 8; i++) {
                float v = acc[i][j] * el[i] * es[j];
                if (typ == txp && i < j) v = 0.f;   // mask s > l
                MsT[(s0 + j) * 132 + l0 + i] = v;
            }
    }
    __syncthreads();

    // ---- phase 2: Y_diag = M @ X  ([128x128]@[128x32]) ----
    {
        const int p = tid & 31, lg = tid >> 5;
        const int lb = lg * 16;
        float yacc[16];
#pragma unroll
        for (int i = 0; i < 16; i++) yacc[i] = 0.f;
        for (int s = 0; s < CHK; s++) {
            float xv = Xs[s * 36 + p];
#pragma unroll
            for (int q = 0; q < 4; q++) {
                float4 mm = *(float4*)&MsT[s * 132 + lb + q * 4];
                yacc[q*4+0] += mm.x * xv;
                yacc[q*4+1] += mm.y * xv;
                yacc[q*4+2] += mm.z * xv;
                yacc[q*4+3] += mm.w * xv;
            }
        }
#pragma unroll
        for (int i = 0; i < 16; i++)
            g_y[(m0 + lb + i) * DINNER + h * HDIM + p] = yacc[i];
    }

    // ---- phase 3: states[p][n] = sum_s B[s][n]*decay[s]*X[s][p] ----
    {
        const int n = tid & 63, pg = tid >> 6;
        float st[8];
#pragma unroll
        for (int i = 0; i < 8; i++) st[i] = 0.f;
        for (int s = 0; s < CHK; s++) {
            float w = BsT[n * 132 + s] * sDs[s];
            float4 x0 = *(float4*)&Xs[s * 36 + pg * 8];
            float4 x1 = *(float4*)&Xs[s * 36 + pg * 8 + 4];
            st[0] += w * x0.x; st[1] += w * x0.y; st[2] += w * x0.z; st[3] += w * x0.w;
            st[4] += w * x1.x; st[5] += w * x1.y; st[6] += w * x1.z; st[7] += w * x1.w;
        }
        size_t sb = ((size_t)((b * NCH + c) * NH + h)) * (HDIM * DST);
#pragma unroll
        for (int i = 0; i < 8; i++)
            g_states[sb + (pg * 8 + i) * DST + n] = st[i];
    }
}

// ============================================================
// Kernel 4: sequential inter-chunk state scan. block=(b,h), 512 thr, float4.
// ============================================================
__global__ __launch_bounds__(512)
void scan_kernel()
{
    int b = blockIdx.x >> 5, h = blockIdx.x & 31;
    int tid = threadIdx.x;  // 512 threads * 4 floats = 2048 = HDIM*DST
    float4 S = make_float4(0.f, 0.f, 0.f, 0.f);
    for (int c = 0; c < NCH; c++) {
        size_t base = ((size_t)((b * NCH + c) * NH + h)) * (HDIM * DST);
        float4 stv = *(const float4*)&g_states[base + tid * 4];
        *(float4*)&g_prevs[base + tid * 4] = S;
        float d = g_dc[(b * NCH + c) * NH + h];
        S.x = S.x * d + stv.x;
        S.y = S.y * d + stv.y;
        S.z = S.z * d + stv.z;
        S.w = S.w * d + stv.w;
    }
}

// ============================================================
// Kernel 5: Y_off + D*x skip + SiLU gating -> g_y (gated)
// ============================================================
__global__ __launch_bounds__(256)
void yoff_kernel(const float* __restrict__ Dvec, const float* __restrict__ z_bias)
{
    extern __shared__ float sm[];
    float* Cs = sm;            // [128][68]
    float* Pv = sm + 128*68;   // [32][68]
    float* eA = sm + 128*68 + 32*68;  // [128]

    const int tid = threadIdx.x;
    const int bid = blockIdx.x;
    const int h = bid & 31;
    const int c = (bid >> 5) & 63;
    const int b = bid >> 11;
    const size_t m0 = (size_t)b * LSEQ + (size_t)c * CHK;
    const size_t pbase = ((size_t)((b * NCH + c) * NH + h)) * (HDIM * DST);

    for (int i = tid; i < CHK * DST; i += 256) {
        int l = i >> 6, n = i & 63;
        Cs[l * 68 + n] = g_conv[(m0 + l) * CONVD + DINNER + NH * DST + h * DST + n];
    }
    for (int i = tid; i < HDIM * DST; i += 256) {
        int p = i >> 6, n = i & 63;
        Pv[p * 68 + n] = g_prevs[pbase + i];
    }
    if (tid < CHK)
        eA[tid] = __expf(g_acum[(m0 + tid) * NH + h]);
    __syncthreads();

    const int p = tid & 31, lg = tid >> 5;
    float4 vp[16];
#pragma unroll
    for (int q = 0; q < 16; q++)
        vp[q] = *(float4*)&Pv[p * 68 + q * 4];
    const float Dh = Dvec[h];

#pragma unroll 4
    for (int li = 0; li < 16; li++) {
        int l = lg * 16 + li;
        float acc = 0.f;
#pragma unroll
        for (int q = 0; q < 16; q++) {
            float4 c4 = *(float4*)&Cs[l * 68 + q * 4];
            acc += c4.x * vp[q].x + c4.y * vp[q].y + c4.z * vp[q].z + c4.w * vp[q].w;
        }
        size_t mr = m0 + l;
        int col = h * HDIM + p;
        float xv = g_conv[mr * CONVD + h * HDIM + p];
        float yv = g_y[mr * DINNER + col] + eA[l] * acc + Dh * xv;
        float zz = g_xbcza[mr * NPROJ + CONVD + col] + z_bias[col];
        float sg = 1.f / (1.f + __expf(-zz));
        g_y[mr * DINNER + col] = yv * (zz * sg);
    }
}

// ============================================================
// launch
// ============================================================
extern "C" void kernel_launch(void* const* d_in, const int* in_sizes, int n_in,
                              void* d_out, int out_size)
{
    (void)in_sizes; (void)n_in; (void)out_size;
    const float* u      = (const float*)d_in[0];
    const float* W_in   = (const float*)d_in[1];
    const float* conv_w = (const float*)d_in[2];
    const float* conv_b = (const float*)d_in[3];
    const float* z_bias = (const float*)d_in[4];
    const float* Dv     = (const float*)d_in[5];
    const float* W_out  = (const float*)d_in[6];
    float* out = (float*)d_out;

    float *p_xbcza = nullptr, *p_y = nullptr;
    cudaGetSymbolAddress((void**)&p_xbcza, g_xbcza);
    cudaGetSymbolAddress((void**)&p_y, g_y);

    // kernel 3 needs ~151 KB dynamic smem
    cudaFuncSetAttribute(chunk_kernel, cudaFuncAttributeMaxDynamicSharedMemorySize, 155 * 1024);
    cudaFuncSetAttribute(yoff_kernel,  cudaFuncAttributeMaxDynamicSharedMemorySize, 48 * 1024);

    // 1) in-proj GEMM: xBCzA[M, 6176] = u @ W_in^T
    {
        dim3 grid((NPROJ + 127) / 128, MROWS / 128);
        sgemm_nt<<<grid, 256>>>(u, W_in, p_xbcza, MROWS, NPROJ, DMODEL);
    }
    // 2) causal depthwise conv
    {
        dim3 grid(CONVD / 256, MROWS);
        conv_kernel<<<grid, 256>>>(conv_w, conv_b);
    }
    // 3) per-chunk SSD
    {
        size_t smem = 38656 * sizeof(float);
        chunk_kernel<<<BATCH * NCH * NH, 256, smem>>>();
    }
    // 4) inter-chunk scan
    scan_kernel<<<BATCH * NH, 512>>>();
    // 5) Y_off + skip + gate
    {
        size_t smem = (128 * 68 + 32 * 68 + 128) * sizeof(float);
        yoff_kernel<<<BATCH * NCH * NH, 256, smem>>>(Dv, z_bias);
    }
    // 6) out-proj GEMM: out[M,1024] = y_gated @ W_out^T
    {
        dim3 grid(DMODEL / 128, MROWS / 128);
        sgemm_nt<<<grid, 256>>>(p_y, W_out, out, MROWS, DMODEL, DINNER);
    }
}

// round 5
// speedup vs baseline: 1.7385x; 1.7385x over previous
#include <cuda_runtime.h>
#include <cuda_bf16.h>
#include <math.h>
#include <stdint.h>

// ---------------- problem constants ----------------
#define BATCH  2
#define LSEQ   8192
#define DMODEL 1024
#define NPROJ  6176    // 2*D_INNER + 2*NQK*DSTATE + NV
#define CONVD  5120    // D_INNER + 2*NQK*DSTATE
#define DINNER 1024
#define NH     32
#define DST    64
#define HDIM   32
#define CHK    128
#define NCH    64
#define MROWS  (BATCH*LSEQ)   // 16384

// split-bf16 GEMM constants
#define K3     3072            // 3 * 1024
#define BM     128
#define BN     128
#define BK     64              // 64 bf16 = 128B = one swizzle atom row
#define NSTAGE 4
#define NCHUNK (K3/BK)         // 48
#define NPROJ_PAD 6400

// ---------------- scratch (device globals) --------
__device__ float g_xbcza[(size_t)MROWS * NPROJ];
__device__ float g_conv [(size_t)MROWS * CONVD];
__device__ float g_acum [(size_t)MROWS * NH];
__device__ float g_y    [(size_t)MROWS * DINNER];
__device__ float g_states[(size_t)BATCH*NCH*NH*HDIM*DST];
__device__ float g_prevs [(size_t)BATCH*NCH*NH*HDIM*DST];
__device__ float g_dc   [BATCH*NCH*NH];

__device__ __nv_bfloat16 g_uS   [(size_t)MROWS * K3];
__device__ __nv_bfloat16 g_WinS [(size_t)NPROJ_PAD * K3];
__device__ __nv_bfloat16 g_yS   [(size_t)MROWS * K3];
__device__ __nv_bfloat16 g_WoutS[(size_t)1024 * K3];

// ---------------- helpers ----------------
__device__ __forceinline__ uint32_t smem_u32(const void* p) {
    uint32_t a;
    asm("{ .reg .u64 t; cvta.to.shared.u64 t, %1; cvt.u32.u64 %0, t; }"
        : "=r"(a) : "l"(p));
    return a;
}
#define SW128(o) ((o) ^ (((o) >> 3) & 0x70))

__device__ __forceinline__ void ldsm4(uint32_t* r, uint32_t addr) {
    asm volatile("ldmatrix.sync.aligned.m8n8.x4.shared.b16 {%0,%1,%2,%3}, [%4];"
        : "=r"(r[0]), "=r"(r[1]), "=r"(r[2]), "=r"(r[3]) : "r"(addr));
}
__device__ __forceinline__ void mma16816(float* c, const uint32_t* a,
                                         uint32_t b0, uint32_t b1) {
    asm volatile(
        "mma.sync.aligned.m16n8k16.row.col.f32.bf16.bf16.f32 "
        "{%0,%1,%2,%3}, {%4,%5,%6,%7}, {%8,%9}, {%0,%1,%2,%3};"
        : "+f"(c[0]), "+f"(c[1]), "+f"(c[2]), "+f"(c[3])
        : "r"(a[0]), "r"(a[1]), "r"(a[2]), "r"(a[3]), "r"(b0), "r"(b1));
}

// ============================================================
// split kernels: fp32 [M,1024] -> bf16 [M,3072]
// A-variant: [hi | lo | hi] ; B-variant: [hi | hi | lo]
// so that A' . B' = hi.hi + lo.hi + hi.lo
// ============================================================
__global__ __launch_bounds__(256)
void split3_A(const float* __restrict__ X, __nv_bfloat16* __restrict__ Y)
{
    size_t m = blockIdx.y;
    int k = blockIdx.x * 256 + threadIdx.x;
    float x = X[m * 1024 + k];
    __nv_bfloat16 hi = __float2bfloat16(x);
    __nv_bfloat16 lo = __float2bfloat16(x - __bfloat162float(hi));
    __nv_bfloat16* row = Y + m * (size_t)K3;
    row[k] = hi; row[1024 + k] = lo; row[2048 + k] = hi;
}
__global__ __launch_bounds__(256)
void split3_B(const float* __restrict__ X, __nv_bfloat16* __restrict__ Y)
{
    size_t m = blockIdx.y;
    int k = blockIdx.x * 256 + threadIdx.x;
    float x = X[m * 1024 + k];
    __nv_bfloat16 hi = __float2bfloat16(x);
    __nv_bfloat16 lo = __float2bfloat16(x - __bfloat162float(hi));
    __nv_bfloat16* row = Y + m * (size_t)K3;
    row[k] = hi; row[1024 + k] = hi; row[2048 + k] = lo;
}

// ============================================================
// bf16 warp-MMA GEMM: C[M, ldc](fp32) = A'[M,K3] @ B'[*,K3]^T
// BM=128, BN=128, BK=64, 256 threads (8 warps, 2x4), 4-stage cp.async.
// ============================================================
__global__ __launch_bounds__(256, 1)
void gemm_mma(float* __restrict__ C,
              const __nv_bfloat16* __restrict__ A,
              const __nv_bfloat16* __restrict__ B,
              int N_out, int ldc)
{
    extern __shared__ char smem[];
    const int tid  = threadIdx.x;
    const int wid  = tid >> 5;
    const int lane = tid & 31;
    const int m0 = blockIdx.y * BM;
    const int n0 = blockIdx.x * BN;
    const int wm = (wid >> 2) * 64;   // 0 or 64
    const int wn = (wid & 3) * 32;    // 0,32,64,96

    // per-stage: A tile 128x128B (16KB) + B tile 128x128B (16KB)
    char* tiles = smem;

    auto fill = [&](int chunk) {
        int s = chunk & (NSTAGE - 1);
        char* As = tiles + s * 32768;
        char* Bs = As + 16384;
        const char* Ag = (const char*)(A + (size_t)m0 * K3 + chunk * BK);
        const char* Bg = (const char*)(B + (size_t)n0 * K3 + chunk * BK);
        uint32_t Asb = smem_u32(As), Bsb = smem_u32(Bs);
#pragma unroll
        for (int r = 0; r < 4; r++) {
            int cid = tid + r * 256;           // 0..1023
            int row = cid >> 3, col = cid & 7;
            uint32_t dst = Asb + SW128(row * 128 + col * 16);
            const void* src = Ag + (size_t)row * (K3 * 2) + col * 16;
            asm volatile("cp.async.cg.shared.global [%0], [%1], 16;" :: "r"(dst), "l"(src));
        }
#pragma unroll
        for (int r = 0; r < 4; r++) {
            int cid = tid + r * 256;
            int row = cid >> 3, col = cid & 7;
            uint32_t dst = Bsb + SW128(row * 128 + col * 16);
            const void* src = Bg + (size_t)row * (K3 * 2) + col * 16;
            asm volatile("cp.async.cg.shared.global [%0], [%1], 16;" :: "r"(dst), "l"(src));
        }
        asm volatile("cp.async.commit_group;" ::: "memory");
    };

    float acc[4][4][4];
#pragma unroll
    for (int mi = 0; mi < 4; mi++)
#pragma unroll
        for (int ni = 0; ni < 4; ni++)
#pragma unroll
            for (int r = 0; r < 4; r++) acc[mi][ni][r] = 0.f;

    fill(0); fill(1); fill(2);

    const int lrow = lane & 15;
    const int lcol = lane >> 4;

    for (int i = 0; i < NCHUNK; i++) {
        int s = i & (NSTAGE - 1);
        if (i < NCHUNK - 2)
            asm volatile("cp.async.wait_group 2;" ::: "memory");
        else if (i == NCHUNK - 2)
            asm volatile("cp.async.wait_group 1;" ::: "memory");
        else
            asm volatile("cp.async.wait_group 0;" ::: "memory");
        __syncthreads();

        if (i + 3 < NCHUNK) fill(i + 3);

        uint32_t Asb = smem_u32(tiles + s * 32768);
        uint32_t Bsb = Asb + 16384;

#pragma unroll
        for (int ks = 0; ks < 4; ks++) {
            uint32_t a[4][4], b[2][4];
#pragma unroll
            for (int mi = 0; mi < 4; mi++) {
                int row = wm + mi * 16 + lrow;
                ldsm4(a[mi], Asb + SW128(row * 128 + (ks * 2 + lcol) * 16));
            }
#pragma unroll
            for (int bi = 0; bi < 2; bi++) {
                int row = wn + bi * 16 + lrow;
                ldsm4(b[bi], Bsb + SW128(row * 128 + (ks * 2 + lcol) * 16));
            }
#pragma unroll
            for (int mi = 0; mi < 4; mi++)
#pragma unroll
                for (int ni = 0; ni < 4; ni++) {
                    int bi = ni >> 1, hf = ni & 1;
                    mma16816(acc[mi][ni], a[mi], b[bi][hf], b[bi][2 + hf]);
                }
        }
        __syncthreads();
    }

    // epilogue
    const int gr = lane >> 2;         // 0..7
    const int gc = (lane & 3) * 2;    // 0,2,4,6
#pragma unroll
    for (int mi = 0; mi < 4; mi++) {
        int m = m0 + wm + mi * 16 + gr;
#pragma unroll
        for (int ni = 0; ni < 4; ni++) {
            int n = n0 + wn + ni * 8 + gc;
            if (n < N_out) {
                float2 v0 = make_float2(acc[mi][ni][0], acc[mi][ni][1]);
                float2 v1 = make_float2(acc[mi][ni][2], acc[mi][ni][3]);
                *(float2*)&C[(size_t)m * ldc + n]       = v0;
                *(float2*)&C[(size_t)(m + 8) * ldc + n] = v1;
            }
        }
    }
}

// ============================================================
// depthwise causal conv (DCONV=4) + bias
// ============================================================
__global__ __launch_bounds__(256)
void conv_kernel(const float* __restrict__ cw, const float* __restrict__ cb)
{
    int ch = blockIdx.x * 256 + threadIdx.x;
    int m  = blockIdx.y;
    int t  = m & (LSEQ - 1);

    const float* base = g_xbcza + (size_t)m * NPROJ + ch;
    float acc = cb[ch];
#pragma unroll
    for (int k = 0; k < 4; k++) {
        int tt = t - 3 + k;
        if (tt >= 0)
            acc += cw[ch * 4 + k] * base[(long)(k - 3) * NPROJ];
    }
    g_conv[(size_t)m * CONVD + ch] = acc;
}

// ============================================================
// per-(b,chunk,head) SSD chunk kernel
// ============================================================
__global__ __launch_bounds__(256)
void chunk_kernel()
{
    extern __shared__ float sm[];
    float* CsT = sm;               // [64][132]
    float* BsT = sm + 8448;        // [64][132]
    float* Xs  = sm + 16896;       // [128][36]
    float* MsT = sm + 21504;       // [128][132]
    float* sA  = sm + 38400;       // [128]
    float* sDs = sm + 38528;       // [128]

    const int tid = threadIdx.x;
    const int bid = blockIdx.x;
    const int h = bid & 31;
    const int c = (bid >> 5) & 63;
    const int b = bid >> 11;
    const size_t m0 = (size_t)b * LSEQ + (size_t)c * CHK;

    {
        int n = tid & 63, lb = tid >> 6;
        for (int l = lb; l < CHK; l += 4) {
            const float* row = &g_conv[(m0 + l) * CONVD];
            BsT[n * 132 + l] = row[DINNER + h * DST + n];
            CsT[n * 132 + l] = row[DINNER + NH * DST + h * DST + n];
        }
        int p = tid & 31, lb2 = tid >> 5;
        for (int l = lb2; l < CHK; l += 8)
            Xs[l * 36 + p] = g_conv[(m0 + l) * CONVD + h * HDIM + p];
    }

    if (tid < CHK) {
        float alog = g_xbcza[(m0 + tid) * NPROJ + (CONVD + DINNER) + h];
        float dt = alog > 20.f ? alog : log1pf(expf(alog));
        sA[tid] = dt;
    }
    __syncthreads();
    for (int off = 1; off < CHK; off <<= 1) {
        float v = 0.f;
        if (tid < CHK && tid >= off) v = sA[tid - off];
        __syncthreads();
        if (tid < CHK) sA[tid] += v;
        __syncthreads();
    }
    if (tid < CHK) sA[tid] = -sA[tid];
    __syncthreads();
    float aLast = sA[CHK - 1];
    if (tid < CHK) {
        sDs[tid] = __expf(aLast - sA[tid]);
        g_acum[(m0 + tid) * NH + h] = sA[tid];
    }
    if (tid == 0) g_dc[(b * NCH + c) * NH + h] = __expf(aLast);
    __syncthreads();

    const int txp = tid & 15, typ = tid >> 4;
    const int l0 = typ * 8, s0 = txp * 8;
    if (typ < txp) {
#pragma unroll
        for (int j = 0; j < 8; j++)
#pragma unroll
            for (int i = 0; i < 8; i++)
                MsT[(s0 + j) * 132 + l0 + i] = 0.f;
    } else {
        float acc[8][8];
#pragma unroll
        for (int i = 0; i < 8; i++)
#pragma unroll
            for (int j = 0; j < 8; j++) acc[i][j] = 0.f;

        for (int n = 0; n < DST; n++) {
            float a[8], bb[8];
            float4 t0 = *(float4*)&CsT[n * 132 + l0];
            float4 t1 = *(float4*)&CsT[n * 132 + l0 + 4];
            float4 u0 = *(float4*)&BsT[n * 132 + s0];
            float4 u1 = *(float4*)&BsT[n * 132 + s0 + 4];
            a[0]=t0.x; a[1]=t0.y; a[2]=t0.z; a[3]=t0.w;
            a[4]=t1.x; a[5]=t1.y; a[6]=t1.z; a[7]=t1.w;
            bb[0]=u0.x; bb[1]=u0.y; bb[2]=u0.z; bb[3]=u0.w;
            bb[4]=u1.x; bb[5]=u1.y; bb[6]=u1.z; bb[7]=u1.w;
#pragma unroll
            for (int i = 0; i < 8; i++)
#pragma unroll
                for (int j = 0; j < 8; j++)
                    acc[i][j] += a[i] * bb[j];
        }
        float as0 = sA[s0];
        float el[8], es[8];
#pragma unroll
        for (int i = 0; i < 8; i++) el[i] = __expf(sA[l0 + i] - as0);
#pragma unroll
        for (int j = 0; j < 8; j++) es[j] = __expf(as0 - sA[s0 + j]);
#pragma unroll
        for (int j = 0; j < 8; j++)
#pragma unroll
            for (int i = 0; i < 8; i++) {
                float v = acc[i][j] * el[i] * es[j];
                if (typ == txp && i < j) v = 0.f;
                MsT[(s0 + j) * 132 + l0 + i] = v;
            }
    }
    __syncthreads();

    {
        const int p = tid & 31, lg = tid >> 5;
        const int lb = lg * 16;
        float yacc[16];
#pragma unroll
        for (int i = 0; i < 16; i++) yacc[i] = 0.f;
        for (int s = 0; s < CHK; s++) {
            float xv = Xs[s * 36 + p];
#pragma unroll
            for (int q = 0; q < 4; q++) {
                float4 mm = *(float4*)&MsT[s * 132 + lb + q * 4];
                yacc[q*4+0] += mm.x * xv;
                yacc[q*4+1] += mm.y * xv;
                yacc[q*4+2] += mm.z * xv;
                yacc[q*4+3] += mm.w * xv;
            }
        }
#pragma unroll
        for (int i = 0; i < 16; i++)
            g_y[(m0 + lb + i) * DINNER + h * HDIM + p] = yacc[i];
    }

    {
        const int n = tid & 63, pg = tid >> 6;
        float st[8];
#pragma unroll
        for (int i = 0; i < 8; i++) st[i] = 0.f;
        for (int s = 0; s < CHK; s++) {
            float w = BsT[n * 132 + s] * sDs[s];
            float4 x0 = *(float4*)&Xs[s * 36 + pg * 8];
            float4 x1 = *(float4*)&Xs[s * 36 + pg * 8 + 4];
            st[0] += w * x0.x; st[1] += w * x0.y; st[2] += w * x0.z; st[3] += w * x0.w;
            st[4] += w * x1.x; st[5] += w * x1.y; st[6] += w * x1.z; st[7] += w * x1.w;
        }
        size_t sb = ((size_t)((b * NCH + c) * NH + h)) * (HDIM * DST);
#pragma unroll
        for (int i = 0; i < 8; i++)
            g_states[sb + (pg * 8 + i) * DST + n] = st[i];
    }
}

// ============================================================
// inter-chunk state scan
// ============================================================
__global__ __launch_bounds__(512)
void scan_kernel()
{
    int b = blockIdx.x >> 5, h = blockIdx.x & 31;
    int tid = threadIdx.x;
    float4 S = make_float4(0.f, 0.f, 0.f, 0.f);
    for (int c = 0; c < NCH; c++) {
        size_t base = ((size_t)((b * NCH + c) * NH + h)) * (HDIM * DST);
        float4 stv = *(const float4*)&g_states[base + tid * 4];
        *(float4*)&g_prevs[base + tid * 4] = S;
        float d = g_dc[(b * NCH + c) * NH + h];
        S.x = S.x * d + stv.x;
        S.y = S.y * d + stv.y;
        S.z = S.z * d + stv.z;
        S.w = S.w * d + stv.w;
    }
}

// ============================================================
// Y_off + D*x skip + SiLU gating
// ============================================================
__global__ __launch_bounds__(256)
void yoff_kernel(const float* __restrict__ Dvec, const float* __restrict__ z_bias)
{
    extern __shared__ float sm[];
    float* Cs = sm;            // [128][68]
    float* Pv = sm + 128*68;   // [32][68]
    float* eA = sm + 128*68 + 32*68;  // [128]

    const int tid = threadIdx.x;
    const int bid = blockIdx.x;
    const int h = bid & 31;
    const int c = (bid >> 5) & 63;
    const int b = bid >> 11;
    const size_t m0 = (size_t)b * LSEQ + (size_t)c * CHK;
    const size_t pbase = ((size_t)((b * NCH + c) * NH + h)) * (HDIM * DST);

    for (int i = tid; i < CHK * DST; i += 256) {
        int l = i >> 6, n = i & 63;
        Cs[l * 68 + n] = g_conv[(m0 + l) * CONVD + DINNER + NH * DST + h * DST + n];
    }
    for (int i = tid; i < HDIM * DST; i += 256) {
        int p = i >> 6, n = i & 63;
        Pv[p * 68 + n] = g_prevs[pbase + i];
    }
    if (tid < CHK)
        eA[tid] = __expf(g_acum[(m0 + tid) * NH + h]);
    __syncthreads();

    const int p = tid & 31, lg = tid >> 5;
    float4 vp[16];
#pragma unroll
    for (int q = 0; q < 16; q++)
        vp[q] = *(float4*)&Pv[p * 68 + q * 4];
    const float Dh = Dvec[h];

#pragma unroll 4
    for (int li = 0; li < 16; li++) {
        int l = lg * 16 + li;
        float acc = 0.f;
#pragma unroll
        for (int q = 0; q < 16; q++) {
            float4 c4 = *(float4*)&Cs[l * 68 + q * 4];
            acc += c4.x * vp[q].x + c4.y * vp[q].y + c4.z * vp[q].z + c4.w * vp[q].w;
        }
        size_t mr = m0 + l;
        int col = h * HDIM + p;
        float xv = g_conv[mr * CONVD + h * HDIM + p];
        float yv = g_y[mr * DINNER + col] + eA[l] * acc + Dh * xv;
        float zz = g_xbcza[mr * NPROJ + CONVD + col] + z_bias[col];
        float sg = 1.f / (1.f + __expf(-zz));
        g_y[mr * DINNER + col] = yv * (zz * sg);
    }
}

// ============================================================
// launch
// ============================================================
extern "C" void kernel_launch(void* const* d_in, const int* in_sizes, int n_in,
                              void* d_out, int out_size)
{
    (void)in_sizes; (void)n_in; (void)out_size;
    const float* u      = (const float*)d_in[0];
    const float* W_in   = (const float*)d_in[1];
    const float* conv_w = (const float*)d_in[2];
    const float* conv_b = (const float*)d_in[3];
    const float* z_bias = (const float*)d_in[4];
    const float* Dv     = (const float*)d_in[5];
    const float* W_out  = (const float*)d_in[6];
    float* out = (float*)d_out;

    float *p_xbcza = nullptr, *p_y = nullptr;
    __nv_bfloat16 *p_uS = nullptr, *p_WinS = nullptr, *p_yS = nullptr, *p_WoutS = nullptr;
    cudaGetSymbolAddress((void**)&p_xbcza, g_xbcza);
    cudaGetSymbolAddress((void**)&p_y, g_y);
    cudaGetSymbolAddress((void**)&p_uS, g_uS);
    cudaGetSymbolAddress((void**)&p_WinS, g_WinS);
    cudaGetSymbolAddress((void**)&p_yS, g_yS);
    cudaGetSymbolAddress((void**)&p_WoutS, g_WoutS);

    static const size_t GEMM_SMEM = NSTAGE * 32768;  // 128 KB
    cudaFuncSetAttribute(gemm_mma, cudaFuncAttributeMaxDynamicSharedMemorySize, (int)GEMM_SMEM);
    cudaFuncSetAttribute(chunk_kernel, cudaFuncAttributeMaxDynamicSharedMemorySize, 155 * 1024);
    cudaFuncSetAttribute(yoff_kernel,  cudaFuncAttributeMaxDynamicSharedMemorySize, 48 * 1024);

    // 0) splits for GEMM1
    split3_A<<<dim3(4, MROWS), 256>>>(u, p_uS);
    split3_B<<<dim3(4, NPROJ), 256>>>(W_in, p_WinS);

    // 1) in-proj GEMM: xBCzA[M, 6176]
    {
        dim3 grid((NPROJ + BN - 1) / BN, MROWS / BM);   // (49, 128)
        gemm_mma<<<grid, 256, GEMM_SMEM>>>(p_xbcza, p_uS, p_WinS, NPROJ, NPROJ);
    }
    // 2) causal depthwise conv
    {
        dim3 grid(CONVD / 256, MROWS);
        conv_kernel<<<grid, 256>>>(conv_w, conv_b);
    }
    // 3) per-chunk SSD
    {
        size_t smem = 38656 * sizeof(float);
        chunk_kernel<<<BATCH * NCH * NH, 256, smem>>>();
    }
    // 4) inter-chunk scan
    scan_kernel<<<BATCH * NH, 512>>>();
    // 5) Y_off + skip + gate
    {
        size_t smem = (128 * 68 + 32 * 68 + 128) * sizeof(float);
        yoff_kernel<<<BATCH * NCH * NH, 256, smem>>>(Dv, z_bias);
    }
    // 6) splits for GEMM2 + out-proj GEMM
    split3_A<<<dim3(4, MROWS), 256>>>(p_y, p_yS);
    split3_B<<<dim3(4, 1024), 256>>>(W_out, p_WoutS);
    {
        dim3 grid(1024 / BN, MROWS / BM);               // (8, 128)
        gemm_mma<<<grid, 256, GEMM_SMEM>>>(out, p_yS, p_WoutS, 1024, 1024);
    }
}

// round 6
// speedup vs baseline: 2.0656x; 1.1882x over previous
#include <cuda_runtime.h>
#include <cuda_bf16.h>
#include <math.h>
#include <stdint.h>

// ---------------- problem constants ----------------
#define BATCH  2
#define LSEQ   8192
#define DMODEL 1024
#define NPROJ  6176    // 2*D_INNER + 2*NQK*DSTATE + NV
#define CONVD  5120    // D_INNER + 2*NQK*DSTATE
#define DINNER 1024
#define NH     32
#define DST    64
#define HDIM   32
#define CHK    128
#define NCH    64
#define MROWS  (BATCH*LSEQ)   // 16384

// split-bf16 GEMM constants
#define K3     3072            // 3 * 1024
#define BM     128
#define BN     128
#define BK     64              // 64 bf16 = 128B = one swizzle atom row
#define NSTAGE 3
#define NCHUNK (K3/BK)         // 48
#define NPROJ_PAD 6400

// ---------------- scratch (device globals) --------
__device__ float g_xbcza[(size_t)MROWS * NPROJ];
__device__ float g_conv [(size_t)MROWS * CONVD];
__device__ float g_acum [(size_t)MROWS * NH];
__device__ float g_y    [(size_t)MROWS * DINNER];   // Y_diag
__device__ float g_states[(size_t)BATCH*NCH*NH*HDIM*DST];
__device__ float g_prevs [(size_t)BATCH*NCH*NH*HDIM*DST];
__device__ float g_dc   [BATCH*NCH*NH];

__device__ __nv_bfloat16 g_uS   [(size_t)MROWS * K3];
__device__ __nv_bfloat16 g_WinS [(size_t)NPROJ_PAD * K3];
__device__ __nv_bfloat16 g_yS   [(size_t)MROWS * K3];
__device__ __nv_bfloat16 g_WoutS[(size_t)1024 * K3];

// ---------------- helpers ----------------
__device__ __forceinline__ uint32_t smem_u32(const void* p) {
    uint32_t a;
    asm("{ .reg .u64 t; cvta.to.shared.u64 t, %1; cvt.u32.u64 %0, t; }"
        : "=r"(a) : "l"(p));
    return a;
}
#define SW128(o) ((o) ^ (((o) >> 3) & 0x70))

__device__ __forceinline__ void ldsm4(uint32_t* r, uint32_t addr) {
    asm volatile("ldmatrix.sync.aligned.m8n8.x4.shared.b16 {%0,%1,%2,%3}, [%4];"
        : "=r"(r[0]), "=r"(r[1]), "=r"(r[2]), "=r"(r[3]) : "r"(addr));
}
__device__ __forceinline__ void mma16816(float* c, const uint32_t* a,
                                         uint32_t b0, uint32_t b1) {
    asm volatile(
        "mma.sync.aligned.m16n8k16.row.col.f32.bf16.bf16.f32 "
        "{%0,%1,%2,%3}, {%4,%5,%6,%7}, {%8,%9}, {%0,%1,%2,%3};"
        : "+f"(c[0]), "+f"(c[1]), "+f"(c[2]), "+f"(c[3])
        : "r"(a[0]), "r"(a[1]), "r"(a[2]), "r"(a[3]), "r"(b0), "r"(b1));
}

// ============================================================
// split kernels (vectorized): fp32 [M,1024] -> bf16 [M,3072]
// A-variant: [hi | lo | hi] ; B-variant: [hi | hi | lo]
// ============================================================
__global__ __launch_bounds__(256)
void split3_Av(const float* __restrict__ X, __nv_bfloat16* __restrict__ Y)
{
    size_t idx = (size_t)blockIdx.x * 256 + threadIdx.x;  // over M*512
    size_t m = idx >> 9;
    int k2 = (int)(idx & 511) * 2;
    float2 x = *(const float2*)&X[m * 1024 + k2];
    __nv_bfloat16 h0 = __float2bfloat16(x.x);
    __nv_bfloat16 h1 = __float2bfloat16(x.y);
    __nv_bfloat16 l0 = __float2bfloat16(x.x - __bfloat162float(h0));
    __nv_bfloat16 l1 = __float2bfloat16(x.y - __bfloat162float(h1));
    __nv_bfloat162 hi; hi.x = h0; hi.y = h1;
    __nv_bfloat162 lo; lo.x = l0; lo.y = l1;
    __nv_bfloat16* row = Y + m * (size_t)K3;
    *(__nv_bfloat162*)&row[k2]        = hi;
    *(__nv_bfloat162*)&row[1024 + k2] = lo;
    *(__nv_bfloat162*)&row[2048 + k2] = hi;
}
__global__ __launch_bounds__(256)
void split3_Bv(const float* __restrict__ X, __nv_bfloat16* __restrict__ Y)
{
    size_t idx = (size_t)blockIdx.x * 256 + threadIdx.x;
    size_t m = idx >> 9;
    int k2 = (int)(idx & 511) * 2;
    float2 x = *(const float2*)&X[m * 1024 + k2];
    __nv_bfloat16 h0 = __float2bfloat16(x.x);
    __nv_bfloat16 h1 = __float2bfloat16(x.y);
    __nv_bfloat16 l0 = __float2bfloat16(x.x - __bfloat162float(h0));
    __nv_bfloat16 l1 = __float2bfloat16(x.y - __bfloat162float(h1));
    __nv_bfloat162 hi; hi.x = h0; hi.y = h1;
    __nv_bfloat162 lo; lo.x = l0; lo.y = l1;
    __nv_bfloat16* row = Y + m * (size_t)K3;
    *(__nv_bfloat162*)&row[k2]        = hi;
    *(__nv_bfloat162*)&row[1024 + k2] = hi;
    *(__nv_bfloat162*)&row[2048 + k2] = lo;
}

// ============================================================
// bf16 warp-MMA GEMM: C[M, ldc](fp32) = A'[M,K3] @ B'[*,K3]^T
// BM=128, BN=128, BK=64, 256 threads (8 warps, 2x4), 3-stage cp.async,
// 2 CTAs/SM.
// ============================================================
__global__ __launch_bounds__(256, 2)
void gemm_mma(float* __restrict__ C,
              const __nv_bfloat16* __restrict__ A,
              const __nv_bfloat16* __restrict__ B,
              int N_out, int ldc)
{
    extern __shared__ char smem[];
    const int tid  = threadIdx.x;
    const int wid  = tid >> 5;
    const int lane = tid & 31;
    const int m0 = blockIdx.y * BM;
    const int n0 = blockIdx.x * BN;
    const int wm = (wid >> 2) * 64;   // 0 or 64
    const int wn = (wid & 3) * 32;    // 0,32,64,96

    char* tiles = smem;   // per-stage: A 16KB + B 16KB

    auto fill = [&](int chunk) {
        int s = chunk % NSTAGE;
        char* As = tiles + s * 32768;
        char* Bs = As + 16384;
        const char* Ag = (const char*)(A + (size_t)m0 * K3 + chunk * BK);
        const char* Bg = (const char*)(B + (size_t)n0 * K3 + chunk * BK);
        uint32_t Asb = smem_u32(As), Bsb = smem_u32(Bs);
#pragma unroll
        for (int r = 0; r < 4; r++) {
            int cid = tid + r * 256;
            int row = cid >> 3, col = cid & 7;
            uint32_t dst = Asb + SW128(row * 128 + col * 16);
            const void* src = Ag + (size_t)row * (K3 * 2) + col * 16;
            asm volatile("cp.async.cg.shared.global [%0], [%1], 16;" :: "r"(dst), "l"(src));
        }
#pragma unroll
        for (int r = 0; r < 4; r++) {
            int cid = tid + r * 256;
            int row = cid >> 3, col = cid & 7;
            uint32_t dst = Bsb + SW128(row * 128 + col * 16);
            const void* src = Bg + (size_t)row * (K3 * 2) + col * 16;
            asm volatile("cp.async.cg.shared.global [%0], [%1], 16;" :: "r"(dst), "l"(src));
        }
        asm volatile("cp.async.commit_group;" ::: "memory");
    };

    float acc[4][4][4];
#pragma unroll
    for (int mi = 0; mi < 4; mi++)
#pragma unroll
        for (int ni = 0; ni < 4; ni++)
#pragma unroll
            for (int r = 0; r < 4; r++) acc[mi][ni][r] = 0.f;

    fill(0); fill(1);

    const int lrow = lane & 15;
    const int lcol = lane >> 4;

    for (int i = 0; i < NCHUNK; i++) {
        int s = i % NSTAGE;
        if (i + 1 < NCHUNK)
            asm volatile("cp.async.wait_group 1;" ::: "memory");
        else
            asm volatile("cp.async.wait_group 0;" ::: "memory");
        __syncthreads();

        if (i + 2 < NCHUNK) fill(i + 2);

        uint32_t Asb = smem_u32(tiles + s * 32768);
        uint32_t Bsb = Asb + 16384;

#pragma unroll
        for (int ks = 0; ks < 4; ks++) {
            uint32_t a[4][4], b[2][4];
#pragma unroll
            for (int mi = 0; mi < 4; mi++) {
                int row = wm + mi * 16 + lrow;
                ldsm4(a[mi], Asb + SW128(row * 128 + (ks * 2 + lcol) * 16));
            }
#pragma unroll
            for (int bi = 0; bi < 2; bi++) {
                int row = wn + bi * 16 + lrow;
                ldsm4(b[bi], Bsb + SW128(row * 128 + (ks * 2 + lcol) * 16));
            }
#pragma unroll
            for (int mi = 0; mi < 4; mi++)
#pragma unroll
                for (int ni = 0; ni < 4; ni++) {
                    int bi = ni >> 1, hf = ni & 1;
                    mma16816(acc[mi][ni], a[mi], b[bi][hf], b[bi][2 + hf]);
                }
        }
    }

    // epilogue
    const int gr = lane >> 2;
    const int gc = (lane & 3) * 2;
#pragma unroll
    for (int mi = 0; mi < 4; mi++) {
        int m = m0 + wm + mi * 16 + gr;
#pragma unroll
        for (int ni = 0; ni < 4; ni++) {
            int n = n0 + wn + ni * 8 + gc;
            if (n < N_out) {
                float2 v0 = make_float2(acc[mi][ni][0], acc[mi][ni][1]);
                float2 v1 = make_float2(acc[mi][ni][2], acc[mi][ni][3]);
                *(float2*)&C[(size_t)m * ldc + n]       = v0;
                *(float2*)&C[(size_t)(m + 8) * ldc + n] = v1;
            }
        }
    }
}

// ============================================================
// depthwise causal conv (DCONV=4) + bias — register-blocked:
// each thread: 4 channels (float4) x 4 timesteps.
// ============================================================
__global__ __launch_bounds__(256)
void conv_kernel(const float* __restrict__ cw, const float* __restrict__ cb)
{
    int c4 = blockIdx.x * 256 + threadIdx.x;   // 0..1279
    int ch = c4 * 4;
    int m0 = blockIdx.y * 4;
    int t0 = m0 & (LSEQ - 1);

    // taps for channels ch..ch+3
    const float4* wp = (const float4*)(cw + ch * 4);
    float4 w0 = wp[0], w1 = wp[1], w2 = wp[2], w3 = wp[3];
    float4 bias = *(const float4*)(cb + ch);

    float4 r[7];
    const float* base = g_xbcza + (size_t)m0 * NPROJ + ch;
#pragma unroll
    for (int k = 0; k < 7; k++) {
        int tt = t0 - 3 + k;
        if (tt >= 0)
            r[k] = *(const float4*)(base + (long)(k - 3) * NPROJ);
        else
            r[k] = make_float4(0.f, 0.f, 0.f, 0.f);
    }

    float* outbase = g_conv + (size_t)m0 * CONVD + ch;
#pragma unroll
    for (int j = 0; j < 4; j++) {
        float4 o = bias;
        o.x += w0.x * r[j].x + w0.y * r[j+1].x + w0.z * r[j+2].x + w0.w * r[j+3].x;
        o.y += w1.x * r[j].y + w1.y * r[j+1].y + w1.z * r[j+2].y + w1.w * r[j+3].y;
        o.z += w2.x * r[j].z + w2.y * r[j+1].z + w2.z * r[j+2].z + w2.w * r[j+3].z;
        o.w += w3.x * r[j].w + w3.y * r[j+1].w + w3.z * r[j+2].w + w3.w * r[j+3].w;
        *(float4*)(outbase + (size_t)j * CONVD) = o;
    }
}

// ============================================================
// per-(b,chunk,head) SSD chunk kernel
// ============================================================
__global__ __launch_bounds__(256)
void chunk_kernel()
{
    extern __shared__ float sm[];
    float* CsT = sm;               // [64][132]
    float* BsT = sm + 8448;        // [64][132]
    float* Xs  = sm + 16896;       // [128][36]
    float* MsT = sm + 21504;       // [128][132]
    float* sA  = sm + 38400;       // [128]
    float* sDs = sm + 38528;       // [128]

    const int tid = threadIdx.x;
    const int bid = blockIdx.x;
    const int h = bid & 31;
    const int c = (bid >> 5) & 63;
    const int b = bid >> 11;
    const size_t m0 = (size_t)b * LSEQ + (size_t)c * CHK;

    {
        int n = tid & 63, lb = tid >> 6;
        for (int l = lb; l < CHK; l += 4) {
            const float* row = &g_conv[(m0 + l) * CONVD];
            BsT[n * 132 + l] = row[DINNER + h * DST + n];
            CsT[n * 132 + l] = row[DINNER + NH * DST + h * DST + n];
        }
        int p = tid & 31, lb2 = tid >> 5;
        for (int l = lb2; l < CHK; l += 8)
            Xs[l * 36 + p] = g_conv[(m0 + l) * CONVD + h * HDIM + p];
    }

    if (tid < CHK) {
        float alog = g_xbcza[(m0 + tid) * NPROJ + (CONVD + DINNER) + h];
        float dt = alog > 20.f ? alog : log1pf(expf(alog));
        sA[tid] = dt;
    }
    __syncthreads();
    for (int off = 1; off < CHK; off <<= 1) {
        float v = 0.f;
        if (tid < CHK && tid >= off) v = sA[tid - off];
        __syncthreads();
        if (tid < CHK) sA[tid] += v;
        __syncthreads();
    }
    if (tid < CHK) sA[tid] = -sA[tid];
    __syncthreads();
    float aLast = sA[CHK - 1];
    if (tid < CHK) {
        sDs[tid] = __expf(aLast - sA[tid]);
        g_acum[(m0 + tid) * NH + h] = sA[tid];
    }
    if (tid == 0) g_dc[(b * NCH + c) * NH + h] = __expf(aLast);
    __syncthreads();

    const int txp = tid & 15, typ = tid >> 4;
    const int l0 = typ * 8, s0 = txp * 8;
    if (typ < txp) {
#pragma unroll
        for (int j = 0; j < 8; j++)
#pragma unroll
            for (int i = 0; i < 8; i++)
                MsT[(s0 + j) * 132 + l0 + i] = 0.f;
    } else {
        float acc[8][8];
#pragma unroll
        for (int i = 0; i < 8; i++)
#pragma unroll
            for (int j = 0; j < 8; j++) acc[i][j] = 0.f;

        for (int n = 0; n < DST; n++) {
            float a[8], bb[8];
            float4 t0 = *(float4*)&CsT[n * 132 + l0];
            float4 t1 = *(float4*)&CsT[n * 132 + l0 + 4];
            float4 u0 = *(float4*)&BsT[n * 132 + s0];
            float4 u1 = *(float4*)&BsT[n * 132 + s0 + 4];
            a[0]=t0.x; a[1]=t0.y; a[2]=t0.z; a[3]=t0.w;
            a[4]=t1.x; a[5]=t1.y; a[6]=t1.z; a[7]=t1.w;
            bb[0]=u0.x; bb[1]=u0.y; bb[2]=u0.z; bb[3]=u0.w;
            bb[4]=u1.x; bb[5]=u1.y; bb[6]=u1.z; bb[7]=u1.w;
#pragma unroll
            for (int i = 0; i < 8; i++)
#pragma unroll
                for (int j = 0; j < 8; j++)
                    acc[i][j] += a[i] * bb[j];
        }
        float as0 = sA[s0];
        float el[8], es[8];
#pragma unroll
        for (int i = 0; i < 8; i++) el[i] = __expf(sA[l0 + i] - as0);
#pragma unroll
        for (int j = 0; j < 8; j++) es[j] = __expf(as0 - sA[s0 + j]);
#pragma unroll
        for (int j = 0; j < 8; j++)
#pragma unroll
            for (int i = 0; i < 8; i++) {
                float v = acc[i][j] * el[i] * es[j];
                if (typ == txp && i < j) v = 0.f;
                MsT[(s0 + j) * 132 + l0 + i] = v;
            }
    }
    __syncthreads();

    {
        const int p = tid & 31, lg = tid >> 5;
        const int lb = lg * 16;
        float yacc[16];
#pragma unroll
        for (int i = 0; i < 16; i++) yacc[i] = 0.f;
        for (int s = 0; s < CHK; s++) {
            float xv = Xs[s * 36 + p];
#pragma unroll
            for (int q = 0; q < 4; q++) {
                float4 mm = *(float4*)&MsT[s * 132 + lb + q * 4];
                yacc[q*4+0] += mm.x * xv;
                yacc[q*4+1] += mm.y * xv;
                yacc[q*4+2] += mm.z * xv;
                yacc[q*4+3] += mm.w * xv;
            }
        }
#pragma unroll
        for (int i = 0; i < 16; i++)
            g_y[(m0 + lb + i) * DINNER + h * HDIM + p] = yacc[i];
    }

    {
        const int n = tid & 63, pg = tid >> 6;
        float st[8];
#pragma unroll
        for (int i = 0; i < 8; i++) st[i] = 0.f;
        for (int s = 0; s < CHK; s++) {
            float w = BsT[n * 132 + s] * sDs[s];
            float4 x0 = *(float4*)&Xs[s * 36 + pg * 8];
            float4 x1 = *(float4*)&Xs[s * 36 + pg * 8 + 4];
            st[0] += w * x0.x; st[1] += w * x0.y; st[2] += w * x0.z; st[3] += w * x0.w;
            st[4] += w * x1.x; st[5] += w * x1.y; st[6] += w * x1.z; st[7] += w * x1.w;
        }
        size_t sb = ((size_t)((b * NCH + c) * NH + h)) * (HDIM * DST);
#pragma unroll
        for (int i = 0; i < 8; i++)
            g_states[sb + (pg * 8 + i) * DST + n] = st[i];
    }
}

// ============================================================
// inter-chunk state scan
// ============================================================
__global__ __launch_bounds__(512)
void scan_kernel()
{
    int b = blockIdx.x >> 5, h = blockIdx.x & 31;
    int tid = threadIdx.x;
    float4 S = make_float4(0.f, 0.f, 0.f, 0.f);
    for (int c = 0; c < NCH; c++) {
        size_t base = ((size_t)((b * NCH + c) * NH + h)) * (HDIM * DST);
        float4 stv = *(const float4*)&g_states[base + tid * 4];
        *(float4*)&g_prevs[base + tid * 4] = S;
        float d = g_dc[(b * NCH + c) * NH + h];
        S.x = S.x * d + stv.x;
        S.y = S.y * d + stv.y;
        S.z = S.z * d + stv.z;
        S.w = S.w * d + stv.w;
    }
}

// ============================================================
// Y_off + D*x skip + SiLU gating, fused bf16 split output -> g_yS
// ============================================================
__global__ __launch_bounds__(256)
void yoff_kernel(const float* __restrict__ Dvec, const float* __restrict__ z_bias)
{
    extern __shared__ float sm[];
    float* Cs = sm;            // [128][68]
    float* Pv = sm + 128*68;   // [32][68]
    float* eA = sm + 128*68 + 32*68;  // [128]

    const int tid = threadIdx.x;
    const int bid = blockIdx.x;
    const int h = bid & 31;
    const int c = (bid >> 5) & 63;
    const int b = bid >> 11;
    const size_t m0 = (size_t)b * LSEQ + (size_t)c * CHK;
    const size_t pbase = ((size_t)((b * NCH + c) * NH + h)) * (HDIM * DST);

    for (int i = tid; i < CHK * DST; i += 256) {
        int l = i >> 6, n = i & 63;
        Cs[l * 68 + n] = g_conv[(m0 + l) * CONVD + DINNER + NH * DST + h * DST + n];
    }
    for (int i = tid; i < HDIM * DST; i += 256) {
        int p = i >> 6, n = i & 63;
        Pv[p * 68 + n] = g_prevs[pbase + i];
    }
    if (tid < CHK)
        eA[tid] = __expf(g_acum[(m0 + tid) * NH + h]);
    __syncthreads();

    const int p = tid & 31, lg = tid >> 5;
    float4 vp[16];
#pragma unroll
    for (int q = 0; q < 16; q++)
        vp[q] = *(float4*)&Pv[p * 68 + q * 4];
    const float Dh = Dvec[h];
    const int col = h * HDIM + p;
    const float zb = z_bias[col];

#pragma unroll 4
    for (int li = 0; li < 16; li++) {
        int l = lg * 16 + li;
        float acc = 0.f;
#pragma unroll
        for (int q = 0; q < 16; q++) {
            float4 c4 = *(float4*)&Cs[l * 68 + q * 4];
            acc += c4.x * vp[q].x + c4.y * vp[q].y + c4.z * vp[q].z + c4.w * vp[q].w;
        }
        size_t mr = m0 + l;
        float xv = g_conv[mr * CONVD + h * HDIM + p];
        float yv = g_y[mr * DINNER + col] + eA[l] * acc + Dh * xv;
        float zz = g_xbcza[mr * NPROJ + CONVD + col] + zb;
        float sg = 1.f / (1.f + __expf(-zz));
        float gv = yv * (zz * sg);
        // fused split: [hi | lo | hi]
        __nv_bfloat16 hi = __float2bfloat16(gv);
        __nv_bfloat16 lo = __float2bfloat16(gv - __bfloat162float(hi));
        __nv_bfloat16* yr = g_yS + mr * (size_t)K3;
        yr[col] = hi; yr[1024 + col] = lo; yr[2048 + col] = hi;
    }
}

// ============================================================
// launch
// ============================================================
extern "C" void kernel_launch(void* const* d_in, const int* in_sizes, int n_in,
                              void* d_out, int out_size)
{
    (void)in_sizes; (void)n_in; (void)out_size;
    const float* u      = (const float*)d_in[0];
    const float* W_in   = (const float*)d_in[1];
    const float* conv_w = (const float*)d_in[2];
    const float* conv_b = (const float*)d_in[3];
    const float* z_bias = (const float*)d_in[4];
    const float* Dv     = (const float*)d_in[5];
    const float* W_out  = (const float*)d_in[6];
    float* out = (float*)d_out;

    float *p_xbcza = nullptr;
    __nv_bfloat16 *p_uS = nullptr, *p_WinS = nullptr, *p_yS = nullptr, *p_WoutS = nullptr;
    cudaGetSymbolAddress((void**)&p_xbcza, g_xbcza);
    cudaGetSymbolAddress((void**)&p_uS, g_uS);
    cudaGetSymbolAddress((void**)&p_WinS, g_WinS);
    cudaGetSymbolAddress((void**)&p_yS, g_yS);
    cudaGetSymbolAddress((void**)&p_WoutS, g_WoutS);

    static const size_t GEMM_SMEM = NSTAGE * 32768;  // 96 KB
    cudaFuncSetAttribute(gemm_mma, cudaFuncAttributeMaxDynamicSharedMemorySize, (int)GEMM_SMEM);
    cudaFuncSetAttribute(chunk_kernel, cudaFuncAttributeMaxDynamicSharedMemorySize, 155 * 1024);
    cudaFuncSetAttribute(yoff_kernel,  cudaFuncAttributeMaxDynamicSharedMemorySize, 48 * 1024);

    // 0) splits for GEMM1
    split3_Av<<<MROWS * 2, 256>>>(u, p_uS);
    split3_Bv<<<NPROJ * 2, 256>>>(W_in, p_WinS);

    // 1) in-proj GEMM: xBCzA[M, 6176]
    {
        dim3 grid((NPROJ + BN - 1) / BN, MROWS / BM);   // (49, 128)
        gemm_mma<<<grid, 256, GEMM_SMEM>>>(p_xbcza, p_uS, p_WinS, NPROJ, NPROJ);
    }
    // 2) causal depthwise conv (register-blocked 4ch x 4t)
    {
        dim3 grid(CONVD / 1024, MROWS / 4);   // (5, 4096)
        conv_kernel<<<grid, 256>>>(conv_w, conv_b);
    }
    // 3) per-chunk SSD
    {
        size_t smem = 38656 * sizeof(float);
        chunk_kernel<<<BATCH * NCH * NH, 256, smem>>>();
    }
    // 4) inter-chunk scan
    scan_kernel<<<BATCH * NH, 512>>>();
    // 5) Y_off + skip + gate (writes bf16 split directly)
    {
        size_t smem = (128 * 68 + 32 * 68 + 128) * sizeof(float);
        yoff_kernel<<<BATCH * NCH * NH, 256, smem>>>(Dv, z_bias);
    }
    // 6) out-proj GEMM
    split3_Bv<<<1024 * 2, 256>>>(W_out, p_WoutS);
    {
        dim3 grid(1024 / BN, MROWS / BM);               // (8, 128)
        gemm_mma<<<grid, 256, GEMM_SMEM>>>(out, p_yS, p_WoutS, 1024, 1024);
    }
}